// round 2
// baseline (speedup 1.0000x reference)
#include <cuda_runtime.h>

// SeqMasking: per-batch compaction of kept tokens (rand > P) to the END of the
// sequence, zeros in the prefix. Gather formulation -> each output element
// written exactly once.
//
// B=64, T=2048, D=256 float32.

#define BB 64
#define TT 2048
#define DD 256
#define PKEEP 0.15f

// Scratch: inverse permutation (rank -> source token) and kept-count per batch.
__device__ int g_src[BB * TT];
__device__ int g_len[BB];

// Kernel 1: one block per batch row. 1024 threads, 2 keep-flags each.
// Block-wide inclusive prefix sum over 2048 flags; emit src[rank]=t and len.
__global__ void __launch_bounds__(1024) seqmask_scan_kernel(const float* __restrict__ rand)
{
    __shared__ int warp_sums[32];
    const int b   = blockIdx.x;
    const int tid = threadIdx.x;

    const float2 rr = reinterpret_cast<const float2*>(rand + b * TT)[tid];
    const int k0 = (rr.x > PKEEP) ? 1 : 0;
    const int k1 = (rr.y > PKEEP) ? 1 : 0;
    const int s  = k0 + k1;
    const int t0 = tid * 2;

    const int lane = tid & 31;
    const int wid  = tid >> 5;

    // inclusive warp scan of s
    int v = s;
    #pragma unroll
    for (int off = 1; off < 32; off <<= 1) {
        int n = __shfl_up_sync(0xffffffffu, v, off);
        if (lane >= off) v += n;
    }
    if (lane == 31) warp_sums[wid] = v;
    __syncthreads();

    // warp 0 scans the 32 warp totals
    if (wid == 0) {
        int w = warp_sums[lane];
        #pragma unroll
        for (int off = 1; off < 32; off <<= 1) {
            int n = __shfl_up_sync(0xffffffffu, w, off);
            if (lane >= off) w += n;
        }
        warp_sums[lane] = w;   // inclusive scan of warp totals
    }
    __syncthreads();

    const int warp_prefix = (wid > 0) ? warp_sums[wid - 1] : 0;
    const int excl = warp_prefix + (v - s);   // exclusive prefix for this thread's pair

    if (k0) g_src[b * TT + excl]      = t0;
    if (k1) g_src[b * TT + excl + k0] = t0 + 1;
    if (tid == 1023) g_len[b] = warp_prefix + v;   // total kept in this batch row
}

// Kernel 2: streaming gather. Each thread handles one float4 of the output.
// out row d (per batch): zeros if d < T - len, else x[b, src[d - (T-len)], :].
__global__ void __launch_bounds__(256) seqmask_gather_kernel(const float* __restrict__ x,
                                                             float* __restrict__ out)
{
    const long long idx = (long long)blockIdx.x * 256 + threadIdx.x;  // float4 index
    const int row = (int)(idx >> 6);   // (b,d) row; 64 float4 per row (D=256)
    const int c   = (int)(idx & 63);
    const int b   = row >> 11;         // / 2048
    const int d   = row & 2047;

    const int len   = __ldg(&g_len[b]);
    const int start = TT - len;

    float4 val;
    if (d < start) {
        val = make_float4(0.f, 0.f, 0.f, 0.f);
    } else {
        const int src = __ldg(&g_src[b * TT + (d - start)]);
        val = __ldg(&reinterpret_cast<const float4*>(x)[((long long)b * TT + src) * 64 + c]);
    }
    reinterpret_cast<float4*>(out)[idx] = val;
}

extern "C" void kernel_launch(void* const* d_in, const int* in_sizes, int n_in,
                              void* d_out, int out_size)
{
    const float* x    = (const float*)d_in[0];   // (B, T, D) float32
    const float* rand = (const float*)d_in[1];   // (B, T)    float32
    float* out        = (float*)d_out;           // (B, T, D) float32

    seqmask_scan_kernel<<<BB, 1024>>>(rand);

    // total float4 elements = B*T*D/4 = 64*2048*64 = 8,388,608 -> 32768 blocks of 256
    const int nblocks = (BB * TT * (DD / 4)) / 256;
    seqmask_gather_kernel<<<nblocks, 256>>>(x, out);
}

// round 3
// speedup vs baseline: 1.1363x; 1.1363x over previous
#include <cuda_runtime.h>

// SeqMasking: per-batch compaction of kept tokens (rand > P) to the END of the
// sequence, zeros in the prefix. Gather formulation, 4 float4 per thread for MLP.
// B=64, T=2048, D=256 float32.

#define BB 64
#define TT 2048
#define DD 256
#define PKEEP 0.15f

__device__ int g_src[BB * TT];
__device__ int g_len[BB];

// Kernel 1: one block per batch row. 1024 threads, 2 keep-flags each.
__global__ void __launch_bounds__(1024) seqmask_scan_kernel(const float* __restrict__ rand)
{
    __shared__ int warp_sums[32];
    const int b   = blockIdx.x;
    const int tid = threadIdx.x;

    const float2 rr = reinterpret_cast<const float2*>(rand + b * TT)[tid];
    const int k0 = (rr.x > PKEEP) ? 1 : 0;
    const int k1 = (rr.y > PKEEP) ? 1 : 0;
    const int s  = k0 + k1;
    const int t0 = tid * 2;

    const int lane = tid & 31;
    const int wid  = tid >> 5;

    int v = s;
    #pragma unroll
    for (int off = 1; off < 32; off <<= 1) {
        int n = __shfl_up_sync(0xffffffffu, v, off);
        if (lane >= off) v += n;
    }
    if (lane == 31) warp_sums[wid] = v;
    __syncthreads();

    if (wid == 0) {
        int w = warp_sums[lane];
        #pragma unroll
        for (int off = 1; off < 32; off <<= 1) {
            int n = __shfl_up_sync(0xffffffffu, w, off);
            if (lane >= off) w += n;
        }
        warp_sums[lane] = w;
    }
    __syncthreads();

    const int warp_prefix = (wid > 0) ? warp_sums[wid - 1] : 0;
    const int excl = warp_prefix + (v - s);

    if (k0) g_src[b * TT + excl]      = t0;
    if (k1) g_src[b * TT + excl + k0] = t0 + 1;
    if (tid == 1023) g_len[b] = warp_prefix + v;
}

// Kernel 2: streaming gather, 4 float4 per thread (4 independent load chains).
// Block covers 1024 consecutive float4 = 16 output rows, all in one batch.
__global__ void __launch_bounds__(256) seqmask_gather_kernel(const float* __restrict__ x,
                                                             float* __restrict__ out)
{
    const int tid = threadIdx.x;
    const long long base = (long long)blockIdx.x * 1024;   // first float4 of block
    const int b = blockIdx.x >> 7;                         // 128 blocks per batch
    const int rowbase = (blockIdx.x & 127) * 16;           // first d-row of block

    const int len   = __ldg(&g_len[b]);
    const int start = TT - len;

    const float4* __restrict__ x4 = reinterpret_cast<const float4*>(x);
    float4* __restrict__ o4       = reinterpret_cast<float4*>(out);
    const int* __restrict__ srcb  = g_src + b * TT;
    const long long xbase = (long long)b * TT * 64;

    float4 v[4];
    #pragma unroll
    for (int j = 0; j < 4; j++) {
        const int f4 = j * 256 + tid;          // 0..1023 within block
        const int d  = rowbase + (f4 >> 6);
        const int c  = f4 & 63;
        if (d < start) {
            v[j] = make_float4(0.f, 0.f, 0.f, 0.f);
        } else {
            const int src = __ldg(&srcb[d - start]);
            v[j] = __ldcs(&x4[xbase + (long long)src * 64 + c]);
        }
    }
    #pragma unroll
    for (int j = 0; j < 4; j++) {
        __stcs(&o4[base + j * 256 + tid], v[j]);
    }
}

extern "C" void kernel_launch(void* const* d_in, const int* in_sizes, int n_in,
                              void* d_out, int out_size)
{
    const float* x    = (const float*)d_in[0];   // (B, T, D) float32
    const float* rand = (const float*)d_in[1];   // (B, T)    float32
    float* out        = (float*)d_out;           // (B, T, D) float32

    seqmask_scan_kernel<<<BB, 1024>>>(rand);

    // total float4 = 64*2048*64 = 8,388,608 ; 1024 per block -> 8192 blocks
    seqmask_gather_kernel<<<8192, 256>>>(x, out);
}

// round 5
// speedup vs baseline: 1.1371x; 1.0007x over previous
#include <cuda_runtime.h>

// SeqMasking: per-batch compaction of kept tokens (rand > P) to the END of the
// sequence, zeros in the prefix. Gather formulation, 8 float4 per thread.
// B=64, T=2048, D=256 float32.

#define BB 64
#define TT 2048
#define DD 256
#define PKEEP 0.15f

__device__ int g_src[BB * TT];
__device__ int g_len[BB];

// Kernel 1: one block per batch row. 512 threads, 4 keep-flags each (float4).
__global__ void __launch_bounds__(512) seqmask_scan_kernel(const float* __restrict__ rand)
{
    __shared__ int warp_sums[16];
    const int b   = blockIdx.x;
    const int tid = threadIdx.x;

    const float4 rr = reinterpret_cast<const float4*>(rand + b * TT)[tid];
    const int k0 = (rr.x > PKEEP) ? 1 : 0;
    const int k1 = (rr.y > PKEEP) ? 1 : 0;
    const int k2 = (rr.z > PKEEP) ? 1 : 0;
    const int k3 = (rr.w > PKEEP) ? 1 : 0;
    const int s  = k0 + k1 + k2 + k3;
    const int t0 = tid * 4;

    const int lane = tid & 31;
    const int wid  = tid >> 5;

    // inclusive warp scan of s
    int v = s;
    #pragma unroll
    for (int off = 1; off < 32; off <<= 1) {
        int n = __shfl_up_sync(0xffffffffu, v, off);
        if (lane >= off) v += n;
    }
    if (lane == 31) warp_sums[wid] = v;
    __syncthreads();

    // warp 0 scans the 16 warp totals
    if (wid == 0 && lane < 16) {
        int w = warp_sums[lane];
        #pragma unroll
        for (int off = 1; off < 16; off <<= 1) {
            int n = __shfl_up_sync(0x0000ffffu, w, off);
            if (lane >= off) w += n;
        }
        warp_sums[lane] = w;
    }
    __syncthreads();

    const int warp_prefix = (wid > 0) ? warp_sums[wid - 1] : 0;
    int pos = warp_prefix + (v - s);   // exclusive prefix for this thread's 4

    int* __restrict__ srcb = g_src + b * TT;
    if (k0) { srcb[pos] = t0;     pos++; }
    if (k1) { srcb[pos] = t0 + 1; pos++; }
    if (k2) { srcb[pos] = t0 + 2; pos++; }
    if (k3) { srcb[pos] = t0 + 3; }
    if (tid == 511) g_len[b] = warp_prefix + v;
}

// Kernel 2: streaming gather, 8 float4 per thread (8 independent load chains).
// Block covers 2048 consecutive float4 = 32 output rows, all in one batch.
__global__ void __launch_bounds__(256) seqmask_gather_kernel(const float* __restrict__ x,
                                                             float* __restrict__ out)
{
    const int tid = threadIdx.x;
    const long long base = (long long)blockIdx.x * 2048;   // first float4 of block
    const int b = blockIdx.x >> 6;                         // 64 blocks per batch
    const int rowbase = (blockIdx.x & 63) * 32;            // first d-row of block

    const int len   = __ldg(&g_len[b]);
    const int start = TT - len;

    const float4* __restrict__ x4 = reinterpret_cast<const float4*>(x);
    float4* __restrict__ o4       = reinterpret_cast<float4*>(out);
    const int* __restrict__ srcb  = g_src + b * TT;
    const long long xbase = (long long)b * TT * 64;

    float4 v[8];
    #pragma unroll
    for (int j = 0; j < 8; j++) {
        const int f4 = j * 256 + tid;          // 0..2047 within block
        const int d  = rowbase + (f4 >> 6);
        const int c  = f4 & 63;
        if (d < start) {
            v[j] = make_float4(0.f, 0.f, 0.f, 0.f);
        } else {
            const int src = __ldg(&srcb[d - start]);
            v[j] = __ldcs(&x4[xbase + (long long)src * 64 + c]);
        }
    }
    #pragma unroll
    for (int j = 0; j < 8; j++) {
        __stcs(&o4[base + j * 256 + tid], v[j]);
    }
}

extern "C" void kernel_launch(void* const* d_in, const int* in_sizes, int n_in,
                              void* d_out, int out_size)
{
    const float* x    = (const float*)d_in[0];   // (B, T, D) float32
    const float* rand = (const float*)d_in[1];   // (B, T)    float32
    float* out        = (float*)d_out;           // (B, T, D) float32

    seqmask_scan_kernel<<<BB, 512>>>(rand);

    // total float4 = 64*2048*64 = 8,388,608 ; 2048 per block -> 4096 blocks
    seqmask_gather_kernel<<<4096, 256>>>(x, out);
}

// round 7
// speedup vs baseline: 1.1379x; 1.0007x over previous
#include <cuda_runtime.h>

// SeqMasking fused: every block recomputes the per-batch keep-scan (8KB of rand,
// L2-resident) and keeps only the 32-entry rank window it needs in SMEM, then
// streams its 32 output rows (8 float4/thread). One kernel, no scratch, no
// inter-kernel dependency.
// B=64, T=2048, D=256 float32.

#define BB 64
#define TT 2048
#define PKEEP 0.15f

__global__ void __launch_bounds__(256) seqmask_fused_kernel(const float* __restrict__ x,
                                                            const float* __restrict__ rand,
                                                            float* __restrict__ out)
{
    __shared__ int warp_sums[8];
    __shared__ int s_src[32];

    const int tid     = threadIdx.x;
    const int b       = blockIdx.x >> 6;          // 64 blocks per batch
    const int rowbase = (blockIdx.x & 63) * 32;   // first d-row of block
    const int lane    = tid & 31;
    const int wid     = tid >> 5;

    // ---- scan phase: 2048 tokens, 8 per thread ----
    const float4* __restrict__ r4 = reinterpret_cast<const float4*>(rand + b * TT);
    const float4 ra = __ldg(&r4[2 * tid]);
    const float4 rb = __ldg(&r4[2 * tid + 1]);

    unsigned m = 0;
    m |= (ra.x > PKEEP) ? 0x01u : 0u;
    m |= (ra.y > PKEEP) ? 0x02u : 0u;
    m |= (ra.z > PKEEP) ? 0x04u : 0u;
    m |= (ra.w > PKEEP) ? 0x08u : 0u;
    m |= (rb.x > PKEEP) ? 0x10u : 0u;
    m |= (rb.y > PKEEP) ? 0x20u : 0u;
    m |= (rb.z > PKEEP) ? 0x40u : 0u;
    m |= (rb.w > PKEEP) ? 0x80u : 0u;
    const int s = __popc(m);

    // inclusive warp scan of s
    int v = s;
    #pragma unroll
    for (int off = 1; off < 32; off <<= 1) {
        int n = __shfl_up_sync(0xffffffffu, v, off);
        if (lane >= off) v += n;
    }
    if (lane == 31) warp_sums[wid] = v;
    __syncthreads();

    // scan of 8 warp totals (warp 0, lanes 0..7)
    if (wid == 0 && lane < 8) {
        int w = warp_sums[lane];
        #pragma unroll
        for (int off = 1; off < 8; off <<= 1) {
            int n = __shfl_up_sync(0x000000ffu, w, off);
            if (lane >= off) w += n;
        }
        warp_sums[lane] = w;   // inclusive
    }
    __syncthreads();

    const int warp_prefix = (wid > 0) ? warp_sums[wid - 1] : 0;
    const int len   = warp_sums[7];
    const int start = TT - len;
    const int lo    = rowbase - start;    // rank of our first row (may be <0)

    // deposit source tokens whose rank falls in [lo, lo+32)
    int r = warp_prefix + (v - s);        // exclusive prefix = rank of first kept token
    const int t0 = tid * 8;
    #pragma unroll
    for (int j = 0; j < 8; j++) {
        if ((m >> j) & 1u) {
            const int rel = r - lo;
            if ((unsigned)rel < 32u) s_src[rel] = t0 + j;
            r++;
        }
    }
    __syncthreads();

    // ---- gather phase: 8 float4 per thread, warp-uniform rows ----
    const float4* __restrict__ x4 = reinterpret_cast<const float4*>(x);
    float4* __restrict__ o4       = reinterpret_cast<float4*>(out);
    const long long xbase = (long long)b * TT * 64;
    const long long obase = (long long)blockIdx.x * 2048;

    float4 val[8];
    #pragma unroll
    for (int j = 0; j < 8; j++) {
        const int f4 = j * 256 + tid;            // 0..2047 within block
        const int i  = f4 >> 6;                  // row index 0..31 within block
        const int c  = f4 & 63;
        const int d  = rowbase + i;
        if (d < start) {
            val[j] = make_float4(0.f, 0.f, 0.f, 0.f);
        } else {
            const int src = s_src[i];
            val[j] = __ldcs(&x4[xbase + (long long)src * 64 + c]);
        }
    }
    #pragma unroll
    for (int j = 0; j < 8; j++) {
        __stcs(&o4[obase + j * 256 + tid], val[j]);
    }
}

extern "C" void kernel_launch(void* const* d_in, const int* in_sizes, int n_in,
                              void* d_out, int out_size)
{
    const float* x    = (const float*)d_in[0];   // (B, T, D) float32
    const float* rand = (const float*)d_in[1];   // (B, T)    float32
    float* out        = (float*)d_out;           // (B, T, D) float32

    // 64 batches x 64 blocks = 4096 blocks; each block: 32 rows x 64 float4
    seqmask_fused_kernel<<<4096, 256>>>(x, rand, out);
}